// round 5
// baseline (speedup 1.0000x reference)
#include <cuda_runtime.h>
#include <cuda_bf16.h>
#include <cstdint>
#include <math.h>

#define EDIM 256
#define NHEAD 8
#define HDIM 32
#define BATCH 4
#define LQ 512
#define LKV 4096
#define NLAYER 4
#define NTQ (LQ*BATCH)     // 2048 query tokens
#define NTKV (LKV*BATCH)   // 16384 kv tokens

// ---------------- scratch (device globals) ----------------
__device__ float g_x  [NTQ*EDIM];
__device__ float g_qh [BATCH*NHEAD*LQ*HDIM];
__device__ float g_kh [BATCH*NHEAD*LKV*HDIM];
__device__ float g_vh [BATCH*NHEAD*LKV*HDIM];
__device__ float g_oh [BATCH*NHEAD*LQ*HDIM];
__device__ float g_t1 [NTQ*EDIM];
__device__ float g_x1 [NTQ*EDIM];
__device__ float g_hh [NTQ*EDIM];
__device__ float g_t2 [NTQ*EDIM];

__global__ void copy_kernel(const float* __restrict__ src, float* __restrict__ dst, int n){
    int i = blockIdx.x*blockDim.x + threadIdx.x;
    if (i < n) dst[i] = src[i];
}

// bf16 two-term split, packed pair (first elem in low 16 bits)
__device__ __forceinline__ void split_pack(float f0, float f1, uint32_t& hi, uint32_t& lo){
    __nv_bfloat16 h0 = __float2bfloat16_rn(f0);
    __nv_bfloat16 h1 = __float2bfloat16_rn(f1);
    __nv_bfloat16 l0 = __float2bfloat16_rn(f0 - __bfloat162float(h0));
    __nv_bfloat16 l1 = __float2bfloat16_rn(f1 - __bfloat162float(h1));
    hi = (uint32_t)__bfloat16_as_ushort(h0) | ((uint32_t)__bfloat16_as_ushort(h1) << 16);
    lo = (uint32_t)__bfloat16_as_ushort(l0) | ((uint32_t)__bfloat16_as_ushort(l1) << 16);
}

// mma.sync m16n8k16 row.col f32 += bf16*bf16
__device__ __forceinline__ void mma16816(float* d, const uint32_t* a, const uint32_t* b){
    asm volatile("mma.sync.aligned.m16n8k16.row.col.f32.bf16.bf16.f32 "
        "{%0,%1,%2,%3}, {%4,%5,%6,%7}, {%8,%9}, {%0,%1,%2,%3};"
        : "+f"(d[0]), "+f"(d[1]), "+f"(d[2]), "+f"(d[3])
        : "r"(a[0]), "r"(a[1]), "r"(a[2]), "r"(a[3]), "r"(b[0]), "r"(b[1]));
}

// ---------------- tensor-core GEMM + bias + scale + rope + head scatter ----------------
// C[t, c] = sum_e A[t,e] W[c,e]; bf16 2-term split (hi*hi + hi*lo + lo*hi).
// 256 threads = 8 warps as 2x4; warp tile 64 rows x 32 cols; block tile 128x128; K staged BK=32.
template<bool ROPE>
__global__ __launch_bounds__(256)
void gemm_rope_tc(const float* __restrict__ A, const float* __restrict__ W,
                  const float* __restrict__ bias, const float* __restrict__ pos,
                  float* __restrict__ out, int L, float scale)
{
    __shared__ uint32_t AS[2][16][136];   // [split][kpair][row]
    __shared__ uint32_t BS[2][16][136];   // [split][kpair][col]

    const int tid  = threadIdx.x;
    const int warp = tid >> 5;
    const int lane = tid & 31;
    const int g    = lane >> 2;
    const int tig  = lane & 3;
    const int wm   = warp >> 2;        // 0..1
    const int wn   = warp & 3;         // 0..3
    const int row0 = blockIdx.x * 128;
    const int col0 = blockIdx.y * 128;

    float acc[4][4][4];                // [m-frag][n-frag][reg]
#pragma unroll
    for (int i = 0; i < 4; i++)
#pragma unroll
        for (int n = 0; n < 4; n++)
#pragma unroll
            for (int x = 0; x < 4; x++) acc[i][n][x] = 0.f;

    for (int k0 = 0; k0 < EDIM; k0 += 32) {
        __syncthreads();
        {
            int r  = tid >> 1;
            int ks = (tid & 1) * 16;
            const float* ar = A + (size_t)(row0 + r)*EDIM + k0 + ks;
            const float* br = W + (size_t)(col0 + r)*EDIM + k0 + ks;
#pragma unroll
            for (int j = 0; j < 4; j++) {
                float4 fa = *(const float4*)(ar + j*4);
                split_pack(fa.x, fa.y, AS[0][(ks>>1)+j*2  ][r], AS[1][(ks>>1)+j*2  ][r]);
                split_pack(fa.z, fa.w, AS[0][(ks>>1)+j*2+1][r], AS[1][(ks>>1)+j*2+1][r]);
                float4 fb = *(const float4*)(br + j*4);
                split_pack(fb.x, fb.y, BS[0][(ks>>1)+j*2  ][r], BS[1][(ks>>1)+j*2  ][r]);
                split_pack(fb.z, fb.w, BS[0][(ks>>1)+j*2+1][r], BS[1][(ks>>1)+j*2+1][r]);
            }
        }
        __syncthreads();

#pragma unroll
        for (int kc = 0; kc < 2; kc++) {
            uint32_t bh[4][2], bl[4][2];
#pragma unroll
            for (int n = 0; n < 4; n++) {
                int c = wn*32 + n*8 + g;
                bh[n][0] = BS[0][kc*8 + tig    ][c];
                bh[n][1] = BS[0][kc*8 + 4 + tig][c];
                bl[n][0] = BS[1][kc*8 + tig    ][c];
                bl[n][1] = BS[1][kc*8 + 4 + tig][c];
            }
#pragma unroll
            for (int i = 0; i < 4; i++) {
                uint32_t ah[4], al[4];
#pragma unroll
                for (int part = 0; part < 4; part++) {
                    int r  = wm*64 + i*16 + g + (part & 1)*8;
                    int kp = kc*8 + (part >> 1)*4 + tig;
                    ah[part] = AS[0][kp][r];
                    al[part] = AS[1][kp][r];
                }
#pragma unroll
                for (int n = 0; n < 4; n++) {
                    mma16816(acc[i][n], ah, bh[n]);
                    mma16816(acc[i][n], ah, bl[n]);
                    mma16816(acc[i][n], al, bh[n]);
                }
            }
        }
    }

    // ---- epilogue: bias + scale + rope + head scatter ----
#pragma unroll
    for (int i = 0; i < 4; i++) {
#pragma unroll
        for (int n = 0; n < 4; n++) {
            int c  = col0 + wn*32 + n*8 + tig*2;   // even
            int h  = c >> 5;
            int d  = c & 31;
            float b0 = bias[c], b1 = bias[c+1];
#pragma unroll
            for (int half = 0; half < 2; half++) {
                int t  = row0 + wm*64 + i*16 + g + half*8;
                int l  = t >> 2;
                int bb = t & 3;
                float v0 = (acc[i][n][half*2+0] + b0) * scale;
                float v1 = (acc[i][n][half*2+1] + b1) * scale;
                if (ROPE) {
                    const float* pp = pos + ((size_t)(bb*L + l)*EDIM + c)*2;
                    float4 cs = *(const float4*)pp;   // cos_e,sin_e,cos_o,sin_o
                    float ve = v0, vo = v1;
                    v0 = ve*cs.x - vo*cs.y;
                    v1 = vo*cs.z + ve*cs.w;
                }
                *(float2*)(out + ((size_t)(bb*NHEAD + h)*L + l)*HDIM + d) = make_float2(v0, v1);
            }
        }
    }
}

// ---------------- scalar generic GEMM (AHEADS fused reshape) ----------------
template<bool RELU, bool RES, bool AHEADS>
__global__ __launch_bounds__(256)
void gemm_gen_kernel(const float* __restrict__ A, const float* __restrict__ W,
                     const float* __restrict__ bias, const float* __restrict__ res,
                     float* __restrict__ out)
{
    const int row0 = blockIdx.x * 64;
    const int col0 = blockIdx.y * 64;
    __shared__ float As[32][68];
    __shared__ float Bs[32][68];
    const int tid = threadIdx.x;
    const int ty = tid >> 4, tx = tid & 15;

    float acc[4][4];
#pragma unroll
    for (int i = 0; i < 4; i++)
#pragma unroll
        for (int j = 0; j < 4; j++) acc[i][j] = 0.f;

    for (int k0 = 0; k0 < EDIM; k0 += 32) {
#pragma unroll
        for (int s = 0; s < 2; s++) {
            int f = tid + s*256;
            int r  = f >> 3;
            int kq = (f & 7) << 2;
            float4 av;
            if (AHEADS) {
                int t = row0 + r;
                int l = t >> 2, bb = t & 3;
                int e = k0 + kq;
                int h = e >> 5, d = e & 31;
                av = *(const float4*)(A + (((size_t)(bb*NHEAD + h))*LQ + l)*HDIM + d);
            } else {
                av = *(const float4*)(A + (size_t)(row0 + r)*EDIM + k0 + kq);
            }
            As[kq+0][r]=av.x; As[kq+1][r]=av.y; As[kq+2][r]=av.z; As[kq+3][r]=av.w;
            float4 bv = *(const float4*)(W + (size_t)(col0 + r)*EDIM + k0 + kq);
            Bs[kq+0][r]=bv.x; Bs[kq+1][r]=bv.y; Bs[kq+2][r]=bv.z; Bs[kq+3][r]=bv.w;
        }
        __syncthreads();
#pragma unroll
        for (int k = 0; k < 32; k++) {
            float a[4], b[4];
            *(float4*)&a[0] = *(const float4*)&As[k][ty*4];
            *(float4*)&b[0] = *(const float4*)&Bs[k][tx*4];
#pragma unroll
            for (int i = 0; i < 4; i++)
#pragma unroll
                for (int j = 0; j < 4; j++)
                    acc[i][j] = fmaf(a[i], b[j], acc[i][j]);
        }
        __syncthreads();
    }

#pragma unroll
    for (int i = 0; i < 4; i++) {
        int t = row0 + ty*4 + i;
#pragma unroll
        for (int j = 0; j < 4; j++) {
            int c = col0 + tx*4 + j;
            float v = acc[i][j] + bias[c];
            if (RES)  v += res[(size_t)t*EDIM + c];
            if (RELU) v = fmaxf(v, 0.f);
            out[(size_t)t*EDIM + c] = v;
        }
    }
}

// ---------------- mma.sync flash attention (bf16 2-term split, max-free softmax) ----------------
__global__ __launch_bounds__(256)
void attn_mma_kernel(const float* __restrict__ Q, const float* __restrict__ K,
                     const float* __restrict__ V, float* __restrict__ O)
{
    __shared__ uint32_t KS[2][16][72];   // [split][d-pair][kv]
    __shared__ uint32_t VS[2][32][40];   // [split][kv-pair][d]

    const int tid  = threadIdx.x;
    const int warp = tid >> 5;
    const int lane = tid & 31;
    const int g    = lane >> 2;
    const int tig  = lane & 3;
    const int bh   = blockIdx.y;
    const int q0   = blockIdx.x * 128;

    const float* qbase = Q + ((size_t)bh*LQ + q0 + warp*16)*HDIM;
    uint32_t qa_hi[2][4], qa_lo[2][4];
#pragma unroll
    for (int kc = 0; kc < 2; kc++)
#pragma unroll
        for (int part = 0; part < 4; part++) {
            int r = g + (part & 1)*8;
            int d = kc*16 + (part >> 1)*8 + tig*2;
            float2 f = *(const float2*)(qbase + (size_t)r*HDIM + d);
            split_pack(f.x, f.y, qa_hi[kc][part], qa_lo[kc][part]);
        }

    float oacc[4][4];
#pragma unroll
    for (int n = 0; n < 4; n++)
#pragma unroll
        for (int x = 0; x < 4; x++) oacc[n][x] = 0.f;
    float lsum0 = 0.f, lsum8 = 0.f;

    for (int kv0 = 0; kv0 < LKV; kv0 += 64) {
        __syncthreads();
        {
            int r = tid >> 2;
            int dseg = (tid & 3) * 8;
            const float* krow = K + ((size_t)bh*LKV + kv0 + r)*HDIM + dseg;
            float4 f0 = *(const float4*)(krow);
            float4 f1 = *(const float4*)(krow + 4);
            int p = dseg >> 1;
            split_pack(f0.x, f0.y, KS[0][p+0][r], KS[1][p+0][r]);
            split_pack(f0.z, f0.w, KS[0][p+1][r], KS[1][p+1][r]);
            split_pack(f1.x, f1.y, KS[0][p+2][r], KS[1][p+2][r]);
            split_pack(f1.z, f1.w, KS[0][p+3][r], KS[1][p+3][r]);
        }
        {
            int kp = tid >> 3;
            int dseg = (tid & 7) * 4;
            const float* v0 = V + ((size_t)bh*LKV + kv0 + 2*kp)*HDIM + dseg;
            float4 a = *(const float4*)(v0);
            float4 b = *(const float4*)(v0 + HDIM);
            split_pack(a.x, b.x, VS[0][kp][dseg+0], VS[1][kp][dseg+0]);
            split_pack(a.y, b.y, VS[0][kp][dseg+1], VS[1][kp][dseg+1]);
            split_pack(a.z, b.z, VS[0][kp][dseg+2], VS[1][kp][dseg+2]);
            split_pack(a.w, b.w, VS[0][kp][dseg+3], VS[1][kp][dseg+3]);
        }
        __syncthreads();

        float sc[8][4];
#pragma unroll
        for (int j = 0; j < 8; j++)
#pragma unroll
            for (int x = 0; x < 4; x++) sc[j][x] = 0.f;
#pragma unroll
        for (int kc = 0; kc < 2; kc++) {
#pragma unroll
            for (int j = 0; j < 8; j++) {
                uint32_t bhf[2] = { KS[0][kc*8+tig][j*8+g], KS[0][kc*8+tig+4][j*8+g] };
                uint32_t blf[2] = { KS[1][kc*8+tig][j*8+g], KS[1][kc*8+tig+4][j*8+g] };
                mma16816(sc[j], qa_hi[kc], bhf);
                mma16816(sc[j], qa_hi[kc], blf);
                mma16816(sc[j], qa_lo[kc], bhf);
            }
        }

#pragma unroll
        for (int j = 0; j < 8; j++) {
            sc[j][0] = __expf(sc[j][0]);
            sc[j][1] = __expf(sc[j][1]);
            sc[j][2] = __expf(sc[j][2]);
            sc[j][3] = __expf(sc[j][3]);
            lsum0 += sc[j][0] + sc[j][1];
            lsum8 += sc[j][2] + sc[j][3];
        }

#pragma unroll
        for (int kc = 0; kc < 4; kc++) {
            uint32_t pa_hi[4], pa_lo[4];
            split_pack(sc[2*kc][0],   sc[2*kc][1],   pa_hi[0], pa_lo[0]);
            split_pack(sc[2*kc][2],   sc[2*kc][3],   pa_hi[1], pa_lo[1]);
            split_pack(sc[2*kc+1][0], sc[2*kc+1][1], pa_hi[2], pa_lo[2]);
            split_pack(sc[2*kc+1][2], sc[2*kc+1][3], pa_hi[3], pa_lo[3]);
#pragma unroll
            for (int n = 0; n < 4; n++) {
                uint32_t vh[2] = { VS[0][kc*8+tig][n*8+g], VS[0][kc*8+tig+4][n*8+g] };
                uint32_t vl[2] = { VS[1][kc*8+tig][n*8+g], VS[1][kc*8+tig+4][n*8+g] };
                mma16816(oacc[n], pa_hi, vh);
                mma16816(oacc[n], pa_hi, vl);
                mma16816(oacc[n], pa_lo, vh);
            }
        }
    }

    lsum0 += __shfl_xor_sync(0xffffffffu, lsum0, 1);
    lsum0 += __shfl_xor_sync(0xffffffffu, lsum0, 2);
    lsum8 += __shfl_xor_sync(0xffffffffu, lsum8, 1);
    lsum8 += __shfl_xor_sync(0xffffffffu, lsum8, 2);
    float inv0 = 1.f / lsum0;
    float inv8 = 1.f / lsum8;

    float* ob = O + ((size_t)bh*LQ + q0 + warp*16)*HDIM;
#pragma unroll
    for (int n = 0; n < 4; n++) {
        int c = n*8 + tig*2;
        *(float2*)(ob + (size_t)g*HDIM + c)     = make_float2(oacc[n][0]*inv0, oacc[n][1]*inv0);
        *(float2*)(ob + (size_t)(g+8)*HDIM + c) = make_float2(oacc[n][2]*inv8, oacc[n][3]*inv8);
    }
}

// ---------------- layernorm ----------------
__global__ void ln_kernel(const float* __restrict__ x, const float* __restrict__ g,
                          const float* __restrict__ b, float* __restrict__ out1,
                          float* __restrict__ out2)
{
    __shared__ float red[8];
    const int t = blockIdx.x, e = threadIdx.x;
    const int w = e >> 5, lane = e & 31;
    float v = x[(size_t)t*EDIM + e];

    float s = v;
#pragma unroll
    for (int off = 16; off; off >>= 1) s += __shfl_xor_sync(0xffffffffu, s, off);
    if (lane == 0) red[w] = s;
    __syncthreads();
    if (e < 32) {
        float r = (lane < 8) ? red[lane] : 0.f;
#pragma unroll
        for (int off = 4; off; off >>= 1) r += __shfl_xor_sync(0xffffffffu, r, off, 8);
        if (lane == 0) red[0] = r;
    }
    __syncthreads();
    float mean = red[0] * (1.f/EDIM);
    __syncthreads();

    float dv = v - mean;
    float s2 = dv*dv;
#pragma unroll
    for (int off = 16; off; off >>= 1) s2 += __shfl_xor_sync(0xffffffffu, s2, off);
    if (lane == 0) red[w] = s2;
    __syncthreads();
    if (e < 32) {
        float r = (lane < 8) ? red[lane] : 0.f;
#pragma unroll
        for (int off = 4; off; off >>= 1) r += __shfl_xor_sync(0xffffffffu, r, off, 8);
        if (lane == 0) red[0] = r;
    }
    __syncthreads();
    float var = red[0] * (1.f/EDIM);

    float y = dv * rsqrtf(var + 1e-5f) * g[e] + b[e];
    out1[(size_t)t*EDIM + e] = y;
    if (out2) out2[(size_t)t*EDIM + e] = y;
}

// ---------------- launch ----------------
extern "C" void kernel_launch(void* const* d_in, const int* in_sizes, int n_in,
                              void* d_out, int out_size)
{
    (void)in_sizes; (void)n_in; (void)out_size;
    const float* query = (const float*)d_in[0];
    const float* value = (const float*)d_in[1];
    const float* qpos  = (const float*)d_in[2];
    const float* vpos  = (const float*)d_in[3];
    const float* Wqkv  = (const float*)d_in[4];
    const float* bqkv  = (const float*)d_in[5];
    const float* Wo    = (const float*)d_in[6];
    const float* bo    = (const float*)d_in[7];
    const float* ln1g  = (const float*)d_in[8];
    const float* ln1b  = (const float*)d_in[9];
    const float* W1    = (const float*)d_in[10];
    const float* b1    = (const float*)d_in[11];
    const float* W2    = (const float*)d_in[12];
    const float* b2    = (const float*)d_in[13];
    const float* ln2g  = (const float*)d_in[14];
    const float* ln2b  = (const float*)d_in[15];
    float* out = (float*)d_out;

    void *px_, *pqh_, *pkh_, *pvh_, *poh_, *pt1_, *px1_, *phh_, *pt2_;
    cudaGetSymbolAddress(&px_,  g_x);
    cudaGetSymbolAddress(&pqh_, g_qh);
    cudaGetSymbolAddress(&pkh_, g_kh);
    cudaGetSymbolAddress(&pvh_, g_vh);
    cudaGetSymbolAddress(&poh_, g_oh);
    cudaGetSymbolAddress(&pt1_, g_t1);
    cudaGetSymbolAddress(&px1_, g_x1);
    cudaGetSymbolAddress(&phh_, g_hh);
    cudaGetSymbolAddress(&pt2_, g_t2);
    float* px  = (float*)px_;
    float* pqh = (float*)pqh_;
    float* pkh = (float*)pkh_;
    float* pvh = (float*)pvh_;
    float* poh = (float*)poh_;
    float* pt1 = (float*)pt1_;
    float* px1 = (float*)px1_;
    float* phh = (float*)phh_;
    float* pt2 = (float*)pt2_;

    copy_kernel<<<NTQ*EDIM/256, 256>>>(query, px, NTQ*EDIM);

    const float scale = 0.17677669529663687f;  // 1/sqrt(32)
    for (int l = 0; l < NLAYER; l++) {
        const float* Wq = Wqkv + (size_t)l*3*EDIM*EDIM;
        const float* Wk = Wq + EDIM*EDIM;
        const float* Wv = Wq + 2*EDIM*EDIM;
        const float* bq = bqkv + (size_t)l*3*EDIM;
        const float* bk = bq + EDIM;
        const float* bv = bq + 2*EDIM;

        gemm_rope_tc<true ><<<dim3(NTQ/128,  2), 256>>>(px,    Wq, bq, qpos,    pqh, LQ,  scale);
        gemm_rope_tc<true ><<<dim3(NTKV/128, 2), 256>>>(value, Wk, bk, vpos,    pkh, LKV, 1.0f);
        gemm_rope_tc<false><<<dim3(NTKV/128, 2), 256>>>(value, Wv, bv, nullptr, pvh, LKV, 1.0f);

        attn_mma_kernel<<<dim3(LQ/128, BATCH*NHEAD), 256>>>(pqh, pkh, pvh, poh);

        gemm_gen_kernel<false,true ,true ><<<dim3(NTQ/64, 4), 256>>>(poh, Wo + (size_t)l*EDIM*EDIM, bo + l*EDIM, px,  pt1);
        ln_kernel<<<NTQ, 256>>>(pt1, ln1g + l*EDIM, ln1b + l*EDIM, px1, nullptr);

        gemm_gen_kernel<true ,false,false><<<dim3(NTQ/64, 4), 256>>>(px1, W1 + (size_t)l*EDIM*EDIM, b1 + l*EDIM, nullptr, phh);
        gemm_gen_kernel<false,true ,false><<<dim3(NTQ/64, 4), 256>>>(phh, W2 + (size_t)l*EDIM*EDIM, b2 + l*EDIM, px1, pt2);
        ln_kernel<<<NTQ, 256>>>(pt2, ln2g + l*EDIM, ln2b + l*EDIM, px, out + (size_t)l*NTQ*EDIM);
    }
}

// round 6
// speedup vs baseline: 1.4866x; 1.4866x over previous
#include <cuda_runtime.h>
#include <cuda_bf16.h>
#include <cstdint>
#include <math.h>

#define EDIM 256
#define NHEAD 8
#define HDIM 32
#define BATCH 4
#define LQ 512
#define LKV 4096
#define NLAYER 4
#define NTQ (LQ*BATCH)     // 2048 query tokens
#define NTKV (LKV*BATCH)   // 16384 kv tokens

// ---------------- scratch (device globals) ----------------
__device__ float g_x  [NTQ*EDIM];
__device__ float g_qh [BATCH*NHEAD*LQ*HDIM];
__device__ float g_kh [BATCH*NHEAD*LKV*HDIM];
__device__ float g_vh [BATCH*NHEAD*LKV*HDIM];
__device__ float g_oh [BATCH*NHEAD*LQ*HDIM];
__device__ float g_t1 [NTQ*EDIM];
__device__ float g_x1 [NTQ*EDIM];
__device__ float g_hh [NTQ*EDIM];
__device__ float g_t2 [NTQ*EDIM];
// pre-split packed bf16-pair buffers (u32 = pair of adjacent-e bf16)
__device__ uint32_t g_vsp_hi[NTKV*EDIM/2];
__device__ uint32_t g_vsp_lo[NTKV*EDIM/2];
__device__ uint32_t g_xsp_hi[NTQ*EDIM/2];
__device__ uint32_t g_xsp_lo[NTQ*EDIM/2];
__device__ uint32_t g_wsp_hi[3*EDIM*EDIM/2];
__device__ uint32_t g_wsp_lo[3*EDIM*EDIM/2];

__global__ void copy_kernel(const float* __restrict__ src, float* __restrict__ dst, int n){
    int i = blockIdx.x*blockDim.x + threadIdx.x;
    if (i < n) dst[i] = src[i];
}

// bf16 two-term split, packed pair (first elem in low 16 bits)
__device__ __forceinline__ void split_pack(float f0, float f1, uint32_t& hi, uint32_t& lo){
    __nv_bfloat16 h0 = __float2bfloat16_rn(f0);
    __nv_bfloat16 h1 = __float2bfloat16_rn(f1);
    __nv_bfloat16 l0 = __float2bfloat16_rn(f0 - __bfloat162float(h0));
    __nv_bfloat16 l1 = __float2bfloat16_rn(f1 - __bfloat162float(h1));
    hi = (uint32_t)__bfloat16_as_ushort(h0) | ((uint32_t)__bfloat16_as_ushort(h1) << 16);
    lo = (uint32_t)__bfloat16_as_ushort(l0) | ((uint32_t)__bfloat16_as_ushort(l1) << 16);
}

// split a float buffer into packed bf16 hi/lo pairs; one thread per float4 (2 pairs)
__global__ void split_kernel(const float* __restrict__ src, uint32_t* __restrict__ hi,
                             uint32_t* __restrict__ lo)
{
    int i = blockIdx.x*256 + threadIdx.x;
    float4 f = ((const float4*)src)[i];
    uint32_t h0,l0,h1,l1;
    split_pack(f.x, f.y, h0, l0);
    split_pack(f.z, f.w, h1, l1);
    ((uint2*)hi)[i] = make_uint2(h0, h1);
    ((uint2*)lo)[i] = make_uint2(l0, l1);
}

// mma.sync m16n8k16 row.col f32 += bf16*bf16
__device__ __forceinline__ void mma16816(float* d, const uint32_t* a, const uint32_t* b){
    asm volatile("mma.sync.aligned.m16n8k16.row.col.f32.bf16.bf16.f32 "
        "{%0,%1,%2,%3}, {%4,%5,%6,%7}, {%8,%9}, {%0,%1,%2,%3};"
        : "+f"(d[0]), "+f"(d[1]), "+f"(d[2]), "+f"(d[3])
        : "r"(a[0]), "r"(a[1]), "r"(a[2]), "r"(a[3]), "r"(b[0]), "r"(b[1]));
}

// ---------------- tensor-core GEMM on pre-split operands + bias/scale/rope/head-scatter ----------------
// A,B given as packed bf16-pair hi/lo u32 arrays [row][e/2]. Block 128x128, BK=32, 8 warps (2x4).
template<bool ROPE>
__global__ __launch_bounds__(256)
void gemm_rope_tc2(const uint32_t* __restrict__ Ahi, const uint32_t* __restrict__ Alo,
                   const uint32_t* __restrict__ Bhi, const uint32_t* __restrict__ Blo,
                   const float* __restrict__ bias, const float* __restrict__ pos,
                   float* __restrict__ out, int L, float scale)
{
    __shared__ uint32_t AS[2][16][136];   // [split][kpair][row]
    __shared__ uint32_t BS[2][16][136];   // [split][kpair][col]

    const int tid  = threadIdx.x;
    const int warp = tid >> 5;
    const int lane = tid & 31;
    const int g    = lane >> 2;
    const int tig  = lane & 3;
    const int wm   = warp >> 2;
    const int wn   = warp & 3;
    const int row0 = blockIdx.x * 128;
    const int col0 = blockIdx.y * 128;

    float acc[4][4][4];
#pragma unroll
    for (int i = 0; i < 4; i++)
#pragma unroll
        for (int n = 0; n < 4; n++)
#pragma unroll
            for (int x = 0; x < 4; x++) acc[i][n][x] = 0.f;

    const int r    = tid >> 1;
    const int half = tid & 1;
    const int kpb  = half * 8;

    for (int k0 = 0; k0 < EDIM; k0 += 32) {
        __syncthreads();
        {
            size_t aoff = (size_t)(row0 + r)*(EDIM/2) + (k0 >> 1) + kpb;
            size_t boff = (size_t)(col0 + r)*(EDIM/2) + (k0 >> 1) + kpb;
            uint4 a0 = *(const uint4*)(Ahi + aoff);
            uint4 a1 = *(const uint4*)(Ahi + aoff + 4);
            AS[0][kpb+0][r]=a0.x; AS[0][kpb+1][r]=a0.y; AS[0][kpb+2][r]=a0.z; AS[0][kpb+3][r]=a0.w;
            AS[0][kpb+4][r]=a1.x; AS[0][kpb+5][r]=a1.y; AS[0][kpb+6][r]=a1.z; AS[0][kpb+7][r]=a1.w;
            uint4 a2 = *(const uint4*)(Alo + aoff);
            uint4 a3 = *(const uint4*)(Alo + aoff + 4);
            AS[1][kpb+0][r]=a2.x; AS[1][kpb+1][r]=a2.y; AS[1][kpb+2][r]=a2.z; AS[1][kpb+3][r]=a2.w;
            AS[1][kpb+4][r]=a3.x; AS[1][kpb+5][r]=a3.y; AS[1][kpb+6][r]=a3.z; AS[1][kpb+7][r]=a3.w;
            uint4 b0 = *(const uint4*)(Bhi + boff);
            uint4 b1 = *(const uint4*)(Bhi + boff + 4);
            BS[0][kpb+0][r]=b0.x; BS[0][kpb+1][r]=b0.y; BS[0][kpb+2][r]=b0.z; BS[0][kpb+3][r]=b0.w;
            BS[0][kpb+4][r]=b1.x; BS[0][kpb+5][r]=b1.y; BS[0][kpb+6][r]=b1.z; BS[0][kpb+7][r]=b1.w;
            uint4 b2 = *(const uint4*)(Blo + boff);
            uint4 b3 = *(const uint4*)(Blo + boff + 4);
            BS[1][kpb+0][r]=b2.x; BS[1][kpb+1][r]=b2.y; BS[1][kpb+2][r]=b2.z; BS[1][kpb+3][r]=b2.w;
            BS[1][kpb+4][r]=b3.x; BS[1][kpb+5][r]=b3.y; BS[1][kpb+6][r]=b3.z; BS[1][kpb+7][r]=b3.w;
        }
        __syncthreads();

#pragma unroll
        for (int kc = 0; kc < 2; kc++) {
            uint32_t bh[4][2], bl[4][2];
#pragma unroll
            for (int n = 0; n < 4; n++) {
                int c = wn*32 + n*8 + g;
                bh[n][0] = BS[0][kc*8 + tig    ][c];
                bh[n][1] = BS[0][kc*8 + 4 + tig][c];
                bl[n][0] = BS[1][kc*8 + tig    ][c];
                bl[n][1] = BS[1][kc*8 + 4 + tig][c];
            }
#pragma unroll
            for (int i = 0; i < 4; i++) {
                uint32_t ah[4], al[4];
#pragma unroll
                for (int part = 0; part < 4; part++) {
                    int rr = wm*64 + i*16 + g + (part & 1)*8;
                    int kp = kc*8 + (part >> 1)*4 + tig;
                    ah[part] = AS[0][kp][rr];
                    al[part] = AS[1][kp][rr];
                }
#pragma unroll
                for (int n = 0; n < 4; n++) {
                    mma16816(acc[i][n], ah, bh[n]);
                    mma16816(acc[i][n], ah, bl[n]);
                    mma16816(acc[i][n], al, bh[n]);
                }
            }
        }
    }

    // ---- epilogue: bias + scale + rope + head scatter ----
#pragma unroll
    for (int i = 0; i < 4; i++) {
#pragma unroll
        for (int n = 0; n < 4; n++) {
            int c  = col0 + wn*32 + n*8 + tig*2;   // even
            int h  = c >> 5;
            int d  = c & 31;
            float b0 = bias[c], b1 = bias[c+1];
#pragma unroll
            for (int hf = 0; hf < 2; hf++) {
                int t  = row0 + wm*64 + i*16 + g + hf*8;
                int l  = t >> 2;
                int bb = t & 3;
                float v0 = (acc[i][n][hf*2+0] + b0) * scale;
                float v1 = (acc[i][n][hf*2+1] + b1) * scale;
                if (ROPE) {
                    const float* pp = pos + ((size_t)(bb*L + l)*EDIM + c)*2;
                    float4 cs = *(const float4*)pp;
                    float ve = v0, vo = v1;
                    v0 = ve*cs.x - vo*cs.y;
                    v1 = vo*cs.z + ve*cs.w;
                }
                *(float2*)(out + ((size_t)(bb*NHEAD + h)*L + l)*HDIM + d) = make_float2(v0, v1);
            }
        }
    }
}

// ---------------- scalar generic GEMM (AHEADS fused reshape) ----------------
template<bool RELU, bool RES, bool AHEADS>
__global__ __launch_bounds__(256)
void gemm_gen_kernel(const float* __restrict__ A, const float* __restrict__ W,
                     const float* __restrict__ bias, const float* __restrict__ res,
                     float* __restrict__ out)
{
    const int row0 = blockIdx.x * 64;
    const int col0 = blockIdx.y * 64;
    __shared__ float As[32][68];
    __shared__ float Bs[32][68];
    const int tid = threadIdx.x;
    const int ty = tid >> 4, tx = tid & 15;

    float acc[4][4];
#pragma unroll
    for (int i = 0; i < 4; i++)
#pragma unroll
        for (int j = 0; j < 4; j++) acc[i][j] = 0.f;

    for (int k0 = 0; k0 < EDIM; k0 += 32) {
#pragma unroll
        for (int s = 0; s < 2; s++) {
            int f = tid + s*256;
            int r  = f >> 3;
            int kq = (f & 7) << 2;
            float4 av;
            if (AHEADS) {
                int t = row0 + r;
                int l = t >> 2, bb = t & 3;
                int e = k0 + kq;
                int h = e >> 5, d = e & 31;
                av = *(const float4*)(A + (((size_t)(bb*NHEAD + h))*LQ + l)*HDIM + d);
            } else {
                av = *(const float4*)(A + (size_t)(row0 + r)*EDIM + k0 + kq);
            }
            As[kq+0][r]=av.x; As[kq+1][r]=av.y; As[kq+2][r]=av.z; As[kq+3][r]=av.w;
            float4 bv = *(const float4*)(W + (size_t)(col0 + r)*EDIM + k0 + kq);
            Bs[kq+0][r]=bv.x; Bs[kq+1][r]=bv.y; Bs[kq+2][r]=bv.z; Bs[kq+3][r]=bv.w;
        }
        __syncthreads();
#pragma unroll
        for (int k = 0; k < 32; k++) {
            float a[4], b[4];
            *(float4*)&a[0] = *(const float4*)&As[k][ty*4];
            *(float4*)&b[0] = *(const float4*)&Bs[k][tx*4];
#pragma unroll
            for (int i = 0; i < 4; i++)
#pragma unroll
                for (int j = 0; j < 4; j++)
                    acc[i][j] = fmaf(a[i], b[j], acc[i][j]);
        }
        __syncthreads();
    }

#pragma unroll
    for (int i = 0; i < 4; i++) {
        int t = row0 + ty*4 + i;
#pragma unroll
        for (int j = 0; j < 4; j++) {
            int c = col0 + tx*4 + j;
            float v = acc[i][j] + bias[c];
            if (RES)  v += res[(size_t)t*EDIM + c];
            if (RELU) v = fmaxf(v, 0.f);
            out[(size_t)t*EDIM + c] = v;
        }
    }
}

// ---------------- mma.sync flash attention (bf16 2-term split, max-free softmax) ----------------
__global__ __launch_bounds__(256)
void attn_mma_kernel(const float* __restrict__ Q, const float* __restrict__ K,
                     const float* __restrict__ V, float* __restrict__ O)
{
    __shared__ uint32_t KS[2][16][72];   // [split][d-pair][kv]
    __shared__ uint32_t VS[2][32][40];   // [split][kv-pair][d]

    const int tid  = threadIdx.x;
    const int warp = tid >> 5;
    const int lane = tid & 31;
    const int g    = lane >> 2;
    const int tig  = lane & 3;
    const int bh   = blockIdx.y;
    const int q0   = blockIdx.x * 128;

    const float* qbase = Q + ((size_t)bh*LQ + q0 + warp*16)*HDIM;
    uint32_t qa_hi[2][4], qa_lo[2][4];
#pragma unroll
    for (int kc = 0; kc < 2; kc++)
#pragma unroll
        for (int part = 0; part < 4; part++) {
            int r = g + (part & 1)*8;
            int d = kc*16 + (part >> 1)*8 + tig*2;
            float2 f = *(const float2*)(qbase + (size_t)r*HDIM + d);
            split_pack(f.x, f.y, qa_hi[kc][part], qa_lo[kc][part]);
        }

    float oacc[4][4];
#pragma unroll
    for (int n = 0; n < 4; n++)
#pragma unroll
        for (int x = 0; x < 4; x++) oacc[n][x] = 0.f;
    float lsum0 = 0.f, lsum8 = 0.f;

    for (int kv0 = 0; kv0 < LKV; kv0 += 64) {
        __syncthreads();
        {
            int r = tid >> 2;
            int dseg = (tid & 3) * 8;
            const float* krow = K + ((size_t)bh*LKV + kv0 + r)*HDIM + dseg;
            float4 f0 = *(const float4*)(krow);
            float4 f1 = *(const float4*)(krow + 4);
            int p = dseg >> 1;
            split_pack(f0.x, f0.y, KS[0][p+0][r], KS[1][p+0][r]);
            split_pack(f0.z, f0.w, KS[0][p+1][r], KS[1][p+1][r]);
            split_pack(f1.x, f1.y, KS[0][p+2][r], KS[1][p+2][r]);
            split_pack(f1.z, f1.w, KS[0][p+3][r], KS[1][p+3][r]);
        }
        {
            int kp = tid >> 3;
            int dseg = (tid & 7) * 4;
            const float* v0 = V + ((size_t)bh*LKV + kv0 + 2*kp)*HDIM + dseg;
            float4 a = *(const float4*)(v0);
            float4 b = *(const float4*)(v0 + HDIM);
            split_pack(a.x, b.x, VS[0][kp][dseg+0], VS[1][kp][dseg+0]);
            split_pack(a.y, b.y, VS[0][kp][dseg+1], VS[1][kp][dseg+1]);
            split_pack(a.z, b.z, VS[0][kp][dseg+2], VS[1][kp][dseg+2]);
            split_pack(a.w, b.w, VS[0][kp][dseg+3], VS[1][kp][dseg+3]);
        }
        __syncthreads();

        float sc[8][4];
#pragma unroll
        for (int j = 0; j < 8; j++)
#pragma unroll
            for (int x = 0; x < 4; x++) sc[j][x] = 0.f;
#pragma unroll
        for (int kc = 0; kc < 2; kc++) {
#pragma unroll
            for (int j = 0; j < 8; j++) {
                uint32_t bhf[2] = { KS[0][kc*8+tig][j*8+g], KS[0][kc*8+tig+4][j*8+g] };
                uint32_t blf[2] = { KS[1][kc*8+tig][j*8+g], KS[1][kc*8+tig+4][j*8+g] };
                mma16816(sc[j], qa_hi[kc], bhf);
                mma16816(sc[j], qa_hi[kc], blf);
                mma16816(sc[j], qa_lo[kc], bhf);
            }
        }

#pragma unroll
        for (int j = 0; j < 8; j++) {
            sc[j][0] = __expf(sc[j][0]);
            sc[j][1] = __expf(sc[j][1]);
            sc[j][2] = __expf(sc[j][2]);
            sc[j][3] = __expf(sc[j][3]);
            lsum0 += sc[j][0] + sc[j][1];
            lsum8 += sc[j][2] + sc[j][3];
        }

#pragma unroll
        for (int kc = 0; kc < 4; kc++) {
            uint32_t pa_hi[4], pa_lo[4];
            split_pack(sc[2*kc][0],   sc[2*kc][1],   pa_hi[0], pa_lo[0]);
            split_pack(sc[2*kc][2],   sc[2*kc][3],   pa_hi[1], pa_lo[1]);
            split_pack(sc[2*kc+1][0], sc[2*kc+1][1], pa_hi[2], pa_lo[2]);
            split_pack(sc[2*kc+1][2], sc[2*kc+1][3], pa_hi[3], pa_lo[3]);
#pragma unroll
            for (int n = 0; n < 4; n++) {
                uint32_t vh[2] = { VS[0][kc*8+tig][n*8+g], VS[0][kc*8+tig+4][n*8+g] };
                uint32_t vl[2] = { VS[1][kc*8+tig][n*8+g], VS[1][kc*8+tig+4][n*8+g] };
                mma16816(oacc[n], pa_hi, vh);
                mma16816(oacc[n], pa_hi, vl);
                mma16816(oacc[n], pa_lo, vh);
            }
        }
    }

    lsum0 += __shfl_xor_sync(0xffffffffu, lsum0, 1);
    lsum0 += __shfl_xor_sync(0xffffffffu, lsum0, 2);
    lsum8 += __shfl_xor_sync(0xffffffffu, lsum8, 1);
    lsum8 += __shfl_xor_sync(0xffffffffu, lsum8, 2);
    float inv0 = 1.f / lsum0;
    float inv8 = 1.f / lsum8;

    float* ob = O + ((size_t)bh*LQ + q0 + warp*16)*HDIM;
#pragma unroll
    for (int n = 0; n < 4; n++) {
        int c = n*8 + tig*2;
        *(float2*)(ob + (size_t)g*HDIM + c)     = make_float2(oacc[n][0]*inv0, oacc[n][1]*inv0);
        *(float2*)(ob + (size_t)(g+8)*HDIM + c) = make_float2(oacc[n][2]*inv8, oacc[n][3]*inv8);
    }
}

// ---------------- layernorm ----------------
__global__ void ln_kernel(const float* __restrict__ x, const float* __restrict__ g,
                          const float* __restrict__ b, float* __restrict__ out1,
                          float* __restrict__ out2)
{
    __shared__ float red[8];
    const int t = blockIdx.x, e = threadIdx.x;
    const int w = e >> 5, lane = e & 31;
    float v = x[(size_t)t*EDIM + e];

    float s = v;
#pragma unroll
    for (int off = 16; off; off >>= 1) s += __shfl_xor_sync(0xffffffffu, s, off);
    if (lane == 0) red[w] = s;
    __syncthreads();
    if (e < 32) {
        float r = (lane < 8) ? red[lane] : 0.f;
#pragma unroll
        for (int off = 4; off; off >>= 1) r += __shfl_xor_sync(0xffffffffu, r, off, 8);
        if (lane == 0) red[0] = r;
    }
    __syncthreads();
    float mean = red[0] * (1.f/EDIM);
    __syncthreads();

    float dv = v - mean;
    float s2 = dv*dv;
#pragma unroll
    for (int off = 16; off; off >>= 1) s2 += __shfl_xor_sync(0xffffffffu, s2, off);
    if (lane == 0) red[w] = s2;
    __syncthreads();
    if (e < 32) {
        float r = (lane < 8) ? red[lane] : 0.f;
#pragma unroll
        for (int off = 4; off; off >>= 1) r += __shfl_xor_sync(0xffffffffu, r, off, 8);
        if (lane == 0) red[0] = r;
    }
    __syncthreads();
    float var = red[0] * (1.f/EDIM);

    float y = dv * rsqrtf(var + 1e-5f) * g[e] + b[e];
    out1[(size_t)t*EDIM + e] = y;
    if (out2) out2[(size_t)t*EDIM + e] = y;
}

// ---------------- launch ----------------
extern "C" void kernel_launch(void* const* d_in, const int* in_sizes, int n_in,
                              void* d_out, int out_size)
{
    (void)in_sizes; (void)n_in; (void)out_size;
    const float* query = (const float*)d_in[0];
    const float* value = (const float*)d_in[1];
    const float* qpos  = (const float*)d_in[2];
    const float* vpos  = (const float*)d_in[3];
    const float* Wqkv  = (const float*)d_in[4];
    const float* bqkv  = (const float*)d_in[5];
    const float* Wo    = (const float*)d_in[6];
    const float* bo    = (const float*)d_in[7];
    const float* ln1g  = (const float*)d_in[8];
    const float* ln1b  = (const float*)d_in[9];
    const float* W1    = (const float*)d_in[10];
    const float* b1    = (const float*)d_in[11];
    const float* W2    = (const float*)d_in[12];
    const float* b2    = (const float*)d_in[13];
    const float* ln2g  = (const float*)d_in[14];
    const float* ln2b  = (const float*)d_in[15];
    float* out = (float*)d_out;

    void *px_, *pqh_, *pkh_, *pvh_, *poh_, *pt1_, *px1_, *phh_, *pt2_;
    void *pvh_hi_, *pvh_lo_, *pxh_, *pxl_, *pwh_, *pwl_;
    cudaGetSymbolAddress(&px_,  g_x);
    cudaGetSymbolAddress(&pqh_, g_qh);
    cudaGetSymbolAddress(&pkh_, g_kh);
    cudaGetSymbolAddress(&pvh_, g_vh);
    cudaGetSymbolAddress(&poh_, g_oh);
    cudaGetSymbolAddress(&pt1_, g_t1);
    cudaGetSymbolAddress(&px1_, g_x1);
    cudaGetSymbolAddress(&phh_, g_hh);
    cudaGetSymbolAddress(&pt2_, g_t2);
    cudaGetSymbolAddress(&pvh_hi_, g_vsp_hi);
    cudaGetSymbolAddress(&pvh_lo_, g_vsp_lo);
    cudaGetSymbolAddress(&pxh_, g_xsp_hi);
    cudaGetSymbolAddress(&pxl_, g_xsp_lo);
    cudaGetSymbolAddress(&pwh_, g_wsp_hi);
    cudaGetSymbolAddress(&pwl_, g_wsp_lo);
    float* px  = (float*)px_;
    float* pqh = (float*)pqh_;
    float* pkh = (float*)pkh_;
    float* pvh = (float*)pvh_;
    float* poh = (float*)poh_;
    float* pt1 = (float*)pt1_;
    float* px1 = (float*)px1_;
    float* phh = (float*)phh_;
    float* pt2 = (float*)pt2_;
    uint32_t* vsp_hi = (uint32_t*)pvh_hi_;
    uint32_t* vsp_lo = (uint32_t*)pvh_lo_;
    uint32_t* xsp_hi = (uint32_t*)pxh_;
    uint32_t* xsp_lo = (uint32_t*)pxl_;
    uint32_t* wsp_hi = (uint32_t*)pwh_;
    uint32_t* wsp_lo = (uint32_t*)pwl_;

    copy_kernel<<<NTQ*EDIM/256, 256>>>(query, px, NTQ*EDIM);
    // pre-split value ONCE (layer-invariant)
    split_kernel<<<NTKV*EDIM/4/256, 256>>>(value, vsp_hi, vsp_lo);

    const float scale = 0.17677669529663687f;  // 1/sqrt(32)
    for (int l = 0; l < NLAYER; l++) {
        const float* Wq = Wqkv + (size_t)l*3*EDIM*EDIM;
        const float* bq = bqkv + (size_t)l*3*EDIM;
        const float* bk = bq + EDIM;
        const float* bv = bq + 2*EDIM;

        // per-layer splits: x (Q-proj A), Wqkv (B operands)
        split_kernel<<<NTQ*EDIM/4/256, 256>>>(px, xsp_hi, xsp_lo);
        split_kernel<<<3*EDIM*EDIM/4/256, 256>>>(Wq, wsp_hi, wsp_lo);
        const uint32_t* wq_hi = wsp_hi;
        const uint32_t* wq_lo = wsp_lo;
        const uint32_t* wk_hi = wsp_hi + EDIM*EDIM/2;
        const uint32_t* wk_lo = wsp_lo + EDIM*EDIM/2;
        const uint32_t* wv_hi = wsp_hi + EDIM*EDIM;
        const uint32_t* wv_lo = wsp_lo + EDIM*EDIM;

        gemm_rope_tc2<true ><<<dim3(NTQ/128,  2), 256>>>(xsp_hi, xsp_lo, wq_hi, wq_lo, bq, qpos,    pqh, LQ,  scale);
        gemm_rope_tc2<true ><<<dim3(NTKV/128, 2), 256>>>(vsp_hi, vsp_lo, wk_hi, wk_lo, bk, vpos,    pkh, LKV, 1.0f);
        gemm_rope_tc2<false><<<dim3(NTKV/128, 2), 256>>>(vsp_hi, vsp_lo, wv_hi, wv_lo, bv, nullptr, pvh, LKV, 1.0f);

        attn_mma_kernel<<<dim3(LQ/128, BATCH*NHEAD), 256>>>(pqh, pkh, pvh, poh);

        gemm_gen_kernel<false,true ,true ><<<dim3(NTQ/64, 4), 256>>>(poh, Wo + (size_t)l*EDIM*EDIM, bo + l*EDIM, px,  pt1);
        ln_kernel<<<NTQ, 256>>>(pt1, ln1g + l*EDIM, ln1b + l*EDIM, px1, nullptr);

        gemm_gen_kernel<true ,false,false><<<dim3(NTQ/64, 4), 256>>>(px1, W1 + (size_t)l*EDIM*EDIM, b1 + l*EDIM, nullptr, phh);
        gemm_gen_kernel<false,true ,false><<<dim3(NTQ/64, 4), 256>>>(phh, W2 + (size_t)l*EDIM*EDIM, b2 + l*EDIM, px1, pt2);
        ln_kernel<<<NTQ, 256>>>(pt2, ln2g + l*EDIM, ln2b + l*EDIM, px, out + (size_t)l*NTQ*EDIM);
    }
}